// round 13
// baseline (speedup 1.0000x reference)
#include <cuda_runtime.h>
#include <cstdint>
#include <math_constants.h>

#define BATCH 4096
#define VSZ   256
#define NU    129
#define SKIP  25
#define NEGINF (-CUDART_INF_F)
#define FULL  0xFFFFFFFFu
#define KEY0  0x80000000u   // fkey(+0.0)

#define ROW_BYTES   516
#define GROUP_ROWS  4
#define GROUP_BYTES 2064                     // 516*4, 16B multiple
#define FIRST_ROW   24                       // 516*24 is 16B aligned
#define NGROUPS     58
#define NSLOTS      3
#define WPB         4

// Strictly monotone float -> uint32 key (order-preserving bijection) + inverse
static __device__ __forceinline__ unsigned fkey(float f) {
    unsigned u = __float_as_uint(f);
    return u ^ ((unsigned)((int)u >> 31) | 0x80000000u);
}
static __device__ __forceinline__ float fkey_inv(unsigned k) {
    unsigned m = (k & 0x80000000u) ? 0x80000000u : 0xFFFFFFFFu;
    return __uint_as_float(k ^ m);
}

static __device__ __forceinline__ uint32_t smem_u32(const void* p) {
    uint32_t a;
    asm("{ .reg .u64 t; cvta.to.shared.u64 t, %1; cvt.u32.u64 %0, t; }" : "=r"(a) : "l"(p));
    return a;
}
static __device__ __forceinline__ void mbar_init(uint32_t mbar, uint32_t cnt) {
    asm volatile("mbarrier.init.shared.b64 [%0], %1;" :: "r"(mbar), "r"(cnt) : "memory");
}
static __device__ __forceinline__ void mbar_expect_tx(uint32_t mbar, uint32_t bytes) {
    asm volatile("mbarrier.arrive.expect_tx.shared.b64 _, [%0], %1;"
                 :: "r"(mbar), "r"(bytes) : "memory");
}
static __device__ __forceinline__ void bulk_g2s(uint32_t dst, const void* src, uint32_t bytes, uint32_t mbar) {
    asm volatile("cp.async.bulk.shared::cta.global.mbarrier::complete_tx::bytes [%0], [%1], %2, [%3];"
                 :: "r"(dst), "l"(src), "r"(bytes), "r"(mbar) : "memory");
}
static __device__ __forceinline__ void mbar_wait(uint32_t mbar, uint32_t parity) {
    uint32_t done;
    asm volatile("{\n\t.reg .pred p;\n\t"
                 "mbarrier.try_wait.parity.acquire.cta.shared::cta.b64 p, [%1], %2;\n\t"
                 "selp.b32 %0, 1, 0, p;\n\t}"
                 : "=r"(done) : "r"(mbar), "r"(parity) : "memory");
    if (!done) {
        asm volatile("{\n\t.reg .pred P1;\n\t"
                     "W_%=:\n\t"
                     "mbarrier.try_wait.parity.acquire.cta.shared::cta.b64 P1, [%0], %1, 0x989680;\n\t"
                     "@P1 bra.uni D_%=;\n\t"
                     "bra.uni W_%=;\n\t"
                     "D_%=:\n\t}"
                     :: "r"(mbar), "r"(parity) : "memory");
    }
}

__global__ void __launch_bounds__(128, 7)
greedy_matching_kernel(const float* __restrict__ x, float* __restrict__ out) {
    __shared__ __align__(128) unsigned char sbuf[WPB][NSLOTS][GROUP_BYTES];
    __shared__ __align__(8)   unsigned long long smbar[WPB][NSLOTS];

    const int wib  = threadIdx.x >> 5;
    const int lane = threadIdx.x & 31;
    const int warp = blockIdx.x * WPB + wib;

    const float* __restrict__ base = x + (size_t)warp * (VSZ * NU);
    float* __restrict__ pi_out = out + BATCH + (size_t)warp * VSZ;

    const uint32_t sb  = smem_u32(&sbuf[wib][0][0]);
    const uint32_t mbb = smem_u32(&smbar[wib][0]);

    // lane 0: init per-warp mbarriers, fence, prime the 3-slot ring (groups 0..2)
    if (lane == 0) {
        mbar_init(mbb + 0, 1); mbar_init(mbb + 8, 1); mbar_init(mbb + 16, 1);
        asm volatile("fence.proxy.async.shared::cta;" ::: "memory");
#pragma unroll
        for (int s = 0; s < NSLOTS; ++s) {
            mbar_expect_tx(mbb + 8u * s, GROUP_BYTES);
            bulk_g2s(sb + s * GROUP_BYTES,
                     base + (size_t)(FIRST_ROW + GROUP_ROWS * s) * NU,
                     GROUP_BYTES, mbb + 8u * s);
        }
    }
    __syncwarp();

    // Skip phase: pi[0..24] = 0 (t = 24 is the skip row inside group 0).
    if (lane <= 24) pi_out[lane] = 0.0f;

    // Ownership: lane l owns j = 1+l, 33+l, 65+l, 97+l (j = 1..128).
    // j = 0 (skip, weight 0, never masked) is folded in via the key space:
    //   fkey(0.0) = KEY0; sel = (gk > KEY0) ? winner : 0.  Tie at +0.0 ->
    //   gk == KEY0 -> skip wins (smallest index), exactly like jnp.argmax.
    float b0 = 0.f, b1 = 0.f, b2 = 0.f, b3 = 0.f;   // 0 = available, -inf = matched
    const unsigned onebit = 1u << lane;
    float size = 0.f;   // per-lane accumulator; butterfly-summed at the end

    // Per-slot lane-based float pointers: all row/col offsets are immediates.
    const float* s0p = (const float*)&sbuf[wib][0][0] + lane;
    const float* s1p = s0p + 516;    // one slot = 516 floats
    const float* s2p = s0p + 1032;

    // One greedy step on slot pointer S at row offset ROFF (= 129*r), step T.
    // Fast path (unique max-key lane): that lane's in-lane strict-'>' argmax
    // is the exact global argmax. Multi-lane key tie: exact min-j fallback.
#define STEP(S, ROFF, T)                                                       \
    do {                                                                       \
        float f0 = (S)[(ROFF) + 1]  + b0;                                      \
        float f1 = (S)[(ROFF) + 33] + b1;                                      \
        float f2 = (S)[(ROFF) + 65] + b2;                                      \
        float f3 = (S)[(ROFF) + 97] + b3;                                      \
        float m01 = fmaxf(f0, f1), m23 = fmaxf(f2, f3);                        \
        float lm  = fmaxf(m01, m23);                                           \
        int jA = (f1 > f0)  ? lane + 33 : lane + 1;                            \
        int jB = (f3 > f2)  ? lane + 97 : lane + 65;                           \
        int li  = (m23 > m01) ? jB : jA;                                       \
        unsigned mk = fkey(lm);                                                \
        unsigned gk = __reduce_max_sync(FULL, mk);                             \
        unsigned eq = __ballot_sync(FULL, mk == gk);                           \
        if (gk > KEY0) {                                                       \
            if (__popc(eq) == 1) {                                             \
                if (eq == onebit) {  /* this lane is the unique winner */      \
                    size += lm;                                                \
                    int tier = (li - 1) >> 5;                                  \
                    if (tier == 0)      b0 = NEGINF;                           \
                    else if (tier == 1) b1 = NEGINF;                           \
                    else if (tier == 2) b2 = NEGINF;                           \
                    else                b3 = NEGINF;                           \
                    pi_out[T] = __int2float_rn(li);                            \
                }                                                              \
            } else {  /* multi-lane key tie: exact first-index */              \
                unsigned cand = (mk == gk) ? (unsigned)li : FULL;              \
                int s = (int)__reduce_min_sync(FULL, cand);                    \
                if (((s - 1) & 31) == lane) {                                  \
                    int tier = (s - 1) >> 5;                                   \
                    if (tier == 0)      b0 = NEGINF;                           \
                    else if (tier == 1) b1 = NEGINF;                           \
                    else if (tier == 2) b2 = NEGINF;                           \
                    else                b3 = NEGINF;                           \
                    size += fkey_inv(gk);                                      \
                }                                                              \
                if (lane == 0) pi_out[T] = __int2float_rn(s);                  \
            }                                                                  \
        } else {  /* best available weight <= 0: take skip (weight 0) */       \
            if (lane == 0) pi_out[T] = 0.0f;                                   \
        }                                                                      \
    } while (0)

#define REFILL(SLOT)                                                           \
    do {                                                                       \
        if (lane == 0) {                                                       \
            mbar_expect_tx(mbb + 8u * (SLOT), GROUP_BYTES);                    \
            bulk_g2s(sb + (SLOT) * GROUP_BYTES, nsrc, GROUP_BYTES,             \
                     mbb + 8u * (SLOT));                                       \
        }                                                                      \
        nsrc += 516;                                                           \
    } while (0)

    // Group 0 (slot 0, rows 24..27): row 24 is skip; consume rows 1..3.
    {
        mbar_wait(mbb + 0, 0);
        STEP(s0p, 129, 25);
        STEP(s0p, 258, 26);
        STEP(s0p, 387, 27);
        if (lane == 0) {   // refill slot 0 with group 3 (rows 36..39)
            mbar_expect_tx(mbb + 0, GROUP_BYTES);
            bulk_g2s(sb + 0, base + (size_t)(FIRST_ROW + 12) * NU,
                     GROUP_BYTES, mbb + 0);
        }
    }

    // Running refill source: group 4 onwards (rows 40..), advances 516 floats.
    const float* nsrc = base + (size_t)(FIRST_ROW + 16) * NU;

    // 19 iterations x 3 groups (slots 1, 2, 0) = groups 1..57.
    // Slot parities: slot1/slot2 use k&1; slot0 (group 3k+3) uses (k+1)&1.
#pragma unroll 1
    for (int k = 0; k < 19; ++k) {
        const int ph = k & 1;
        const int t0 = 28 + 12 * k;
        const bool rf = (k < 18);

        mbar_wait(mbb + 8, ph);
        STEP(s1p, 0,   t0 + 0);
        STEP(s1p, 129, t0 + 1);
        STEP(s1p, 258, t0 + 2);
        STEP(s1p, 387, t0 + 3);
        if (rf) REFILL(1);

        mbar_wait(mbb + 16, ph);
        STEP(s2p, 0,   t0 + 4);
        STEP(s2p, 129, t0 + 5);
        STEP(s2p, 258, t0 + 6);
        STEP(s2p, 387, t0 + 7);
        if (rf) REFILL(2);

        mbar_wait(mbb + 0, ph ^ 1);
        STEP(s0p, 0,   t0 + 8);
        STEP(s0p, 129, t0 + 9);
        STEP(s0p, 258, t0 + 10);
        STEP(s0p, 387, t0 + 11);
        if (rf) REFILL(0);
    }

    // Butterfly-sum the per-lane size accumulators (deterministic order).
#pragma unroll
    for (int o = 16; o; o >>= 1) size += __shfl_xor_sync(FULL, size, o);
    if (lane == 0) out[warp] = -size;
}

extern "C" void kernel_launch(void* const* d_in, const int* in_sizes, int n_in,
                              void* d_out, int out_size) {
    const float* x = (const float*)d_in[0];
    float* out = (float*)d_out;
    greedy_matching_kernel<<<BATCH / WPB, 128>>>(x, out);
}

// round 14
// speedup vs baseline: 1.0244x; 1.0244x over previous
#include <cuda_runtime.h>
#include <cstdint>
#include <math_constants.h>

#define BATCH 4096
#define VSZ   256
#define NU    129
#define SKIP  25
#define NEGINF (-CUDART_INF_F)
#define FULL  0xFFFFFFFFu
#define KEY0  0x80000000u   // fkey(+0.0)

#define ROW_BYTES   516
#define GROUP_ROWS  4
#define GROUP_BYTES 2064                     // 516*4, 16B multiple
#define FIRST_ROW   24                       // 516*24 is 16B aligned
#define NGROUPS     58
#define NSLOTS      3
#define WPB         4

// Strictly monotone float -> uint32 key (order-preserving bijection) + inverse
static __device__ __forceinline__ unsigned fkey(float f) {
    unsigned u = __float_as_uint(f);
    return u ^ ((unsigned)((int)u >> 31) | 0x80000000u);
}
static __device__ __forceinline__ float fkey_inv(unsigned k) {
    unsigned m = (k & 0x80000000u) ? 0x80000000u : 0xFFFFFFFFu;
    return __uint_as_float(k ^ m);
}

static __device__ __forceinline__ uint32_t smem_u32(const void* p) {
    uint32_t a;
    asm("{ .reg .u64 t; cvta.to.shared.u64 t, %1; cvt.u32.u64 %0, t; }" : "=r"(a) : "l"(p));
    return a;
}
static __device__ __forceinline__ void mbar_init(uint32_t mbar, uint32_t cnt) {
    asm volatile("mbarrier.init.shared.b64 [%0], %1;" :: "r"(mbar), "r"(cnt) : "memory");
}
static __device__ __forceinline__ void mbar_expect_tx(uint32_t mbar, uint32_t bytes) {
    asm volatile("mbarrier.arrive.expect_tx.shared.b64 _, [%0], %1;"
                 :: "r"(mbar), "r"(bytes) : "memory");
}
static __device__ __forceinline__ void bulk_g2s(uint32_t dst, const void* src, uint32_t bytes, uint32_t mbar) {
    asm volatile("cp.async.bulk.shared::cta.global.mbarrier::complete_tx::bytes [%0], [%1], %2, [%3];"
                 :: "r"(dst), "l"(src), "r"(bytes), "r"(mbar) : "memory");
}
static __device__ __forceinline__ void mbar_wait(uint32_t mbar, uint32_t parity) {
    uint32_t done;
    asm volatile("{\n\t.reg .pred p;\n\t"
                 "mbarrier.try_wait.parity.acquire.cta.shared::cta.b64 p, [%1], %2;\n\t"
                 "selp.b32 %0, 1, 0, p;\n\t}"
                 : "=r"(done) : "r"(mbar), "r"(parity) : "memory");
    if (!done) {
        asm volatile("{\n\t.reg .pred P1;\n\t"
                     "W_%=:\n\t"
                     "mbarrier.try_wait.parity.acquire.cta.shared::cta.b64 P1, [%0], %1, 0x989680;\n\t"
                     "@P1 bra.uni D_%=;\n\t"
                     "bra.uni W_%=;\n\t"
                     "D_%=:\n\t}"
                     :: "r"(mbar), "r"(parity) : "memory");
    }
}

__global__ void __launch_bounds__(128, 7)
greedy_matching_kernel(const float* __restrict__ x, float* __restrict__ out) {
    __shared__ __align__(128) unsigned char sbuf[WPB][NSLOTS][GROUP_BYTES];
    __shared__ __align__(8)   unsigned long long smbar[WPB][NSLOTS];

    const int wib  = threadIdx.x >> 5;
    const int lane = threadIdx.x & 31;
    const int warp = blockIdx.x * WPB + wib;

    const float* __restrict__ base = x + (size_t)warp * (VSZ * NU);
    float* __restrict__ pi_out = out + BATCH + (size_t)warp * VSZ;

    const uint32_t sb  = smem_u32(&sbuf[wib][0][0]);
    const uint32_t mbb = smem_u32(&smbar[wib][0]);

    // lane 0: init per-warp mbarriers, fence, prime the 3-slot ring (groups 0..2)
    if (lane == 0) {
        mbar_init(mbb + 0, 1); mbar_init(mbb + 8, 1); mbar_init(mbb + 16, 1);
        asm volatile("fence.proxy.async.shared::cta;" ::: "memory");
#pragma unroll
        for (int s = 0; s < NSLOTS; ++s) {
            mbar_expect_tx(mbb + 8u * s, GROUP_BYTES);
            bulk_g2s(sb + s * GROUP_BYTES,
                     base + (size_t)(FIRST_ROW + GROUP_ROWS * s) * NU,
                     GROUP_BYTES, mbb + 8u * s);
        }
    }
    __syncwarp();

    // Skip phase: sel = 0, weight 0, no mask change (t = 0..24).
    if (lane <= 24) pi_out[lane] = 0.0f;

    // Ownership: lane l owns j = 1+l, 33+l, 65+l, 97+l (j = 1..128 only).
    // j = 0 (skip, weight 0, never masked) is folded in via the key space:
    //   fkey(+0.0) = KEY0; sel = (gk > KEY0) ? winner : 0.
    // Ties at 0.0 (incl. -0.0) resolve to skip = index 0 = first max, exactly
    // matching jnp.argmax. Bias: 0 = available, -inf = matched.
    float b0 = 0.f, b1 = 0.f, b2 = 0.f, b3 = 0.f;
    const unsigned onebit = 1u << lane;
    float size = 0.f;   // per-lane accumulator; butterfly-summed at the end

    // One greedy step on smem row `rp`, emitting pi[T].
    // Fast path (unique max-key lane): that lane's in-lane strict-'>' argmax
    // is the exact global argmax; it does bias update, size add (its lm ==
    // selected weight, bit-exact), and the pi store locally — nothing else
    // on the recurrence. Multi-lane key tie (~never on gaussian data):
    // exact first-index via REDUX.min fallback.
#define STEP(rp, T)                                                            \
    do {                                                                       \
        float f0 = (rp)[lane + 1]  + b0;                                       \
        float f1 = (rp)[lane + 33] + b1;                                       \
        float f2 = (rp)[lane + 65] + b2;                                       \
        float f3 = (rp)[lane + 97] + b3;                                       \
        float m01 = fmaxf(f0, f1), m23 = fmaxf(f2, f3);                        \
        float lm  = fmaxf(m01, m23);                                           \
        int jA = (f1 > f0)  ? lane + 33 : lane + 1;                            \
        int jB = (f3 > f2)  ? lane + 97 : lane + 65;                           \
        int li  = (m23 > m01) ? jB : jA;                                       \
        unsigned mk = fkey(lm);                                                \
        unsigned gk = __reduce_max_sync(FULL, mk);                             \
        unsigned eq = __ballot_sync(FULL, mk == gk);                           \
        if (__popc(eq) == 1) {                                                 \
            if (eq == onebit) {  /* unique winner lane does everything */      \
                if (gk > KEY0) {                                               \
                    size += lm;                                                \
                    int tier = (li - 1) >> 5;                                  \
                    if (tier == 0)      b0 = NEGINF;                           \
                    else if (tier == 1) b1 = NEGINF;                           \
                    else if (tier == 2) b2 = NEGINF;                           \
                    else                b3 = NEGINF;                           \
                    pi_out[T] = __int2float_rn(li);                            \
                } else {                                                       \
                    pi_out[T] = 0.0f;   /* skip: weight 0, no mask change */   \
                }                                                              \
            }                                                                  \
        } else {  /* multi-lane key tie: exact first-index */                  \
            unsigned cand = (mk == gk) ? (unsigned)li : FULL;                  \
            int s = (int)__reduce_min_sync(FULL, cand);                        \
            if (gk <= KEY0) s = 0;   /* skip beats any <= 0 max */             \
            if (s != 0 && ((s - 1) & 31) == lane) {                            \
                int tier = (s - 1) >> 5;                                       \
                if (tier == 0)      b0 = NEGINF;                               \
                else if (tier == 1) b1 = NEGINF;                               \
                else if (tier == 2) b2 = NEGINF;                               \
                else                b3 = NEGINF;                               \
                size += fkey_inv(gk);                                          \
            }                                                                  \
            if (lane == 0) pi_out[T] = __int2float_rn(s);                      \
        }                                                                      \
    } while (0)

    int stage = 0, phase = 0;

    // Group 0 (rows 24..27): row 24 is in the skip phase, consume rows 1..3.
    {
        mbar_wait(mbb + 0, 0);
        const unsigned char* sp = &sbuf[wib][0][0];
        STEP((const float*)(sp + 1 * ROW_BYTES), 25);
        STEP((const float*)(sp + 2 * ROW_BYTES), 26);
        STEP((const float*)(sp + 3 * ROW_BYTES), 27);
        if (lane == 0) {  // refill with group 3
            mbar_expect_tx(mbb + 0, GROUP_BYTES);
            bulk_g2s(sb + 0,
                     base + (size_t)(FIRST_ROW + GROUP_ROWS * NSLOTS) * NU,
                     GROUP_BYTES, mbb + 0);
        }
        stage = 1;
    }

    // Groups 1..57: 4 steps each; refill group g+3 while g+3 < 58.
    // Safe: the last STEP's REDUX/ballot converges the warp after every lane's
    // LDS of this slot has produced its value, so lane 0's refill cannot race.
#pragma unroll 1
    for (int g = 1; g < NGROUPS; ++g) {
        mbar_wait(mbb + 8u * stage, phase);
        const unsigned char* sp = &sbuf[wib][stage][0];
        const int t0 = FIRST_ROW + GROUP_ROWS * g;
        STEP((const float*)(sp + 0 * ROW_BYTES), t0 + 0);
        STEP((const float*)(sp + 1 * ROW_BYTES), t0 + 1);
        STEP((const float*)(sp + 2 * ROW_BYTES), t0 + 2);
        STEP((const float*)(sp + 3 * ROW_BYTES), t0 + 3);
        if (lane == 0 && g + NSLOTS < NGROUPS) {
            mbar_expect_tx(mbb + 8u * stage, GROUP_BYTES);
            bulk_g2s(sb + stage * GROUP_BYTES,
                     base + (size_t)(t0 + GROUP_ROWS * NSLOTS) * NU,
                     GROUP_BYTES, mbb + 8u * stage);
        }
        if (++stage == NSLOTS) { stage = 0; phase ^= 1; }
    }

    // Butterfly-sum the per-lane size accumulators (deterministic order).
#pragma unroll
    for (int o = 16; o; o >>= 1) size += __shfl_xor_sync(FULL, size, o);
    if (lane == 0) out[warp] = -size;
}

extern "C" void kernel_launch(void* const* d_in, const int* in_sizes, int n_in,
                              void* d_out, int out_size) {
    const float* x = (const float*)d_in[0];
    float* out = (float*)d_out;
    greedy_matching_kernel<<<BATCH / WPB, 128>>>(x, out);
}